// round 15
// baseline (speedup 1.0000x reference)
#include <cuda_runtime.h>
#include <cuda_bf16.h>

// relu(segment_sum(x @ W^T + b))  ==  relu(segment_sum(x) @ W^T + count * b)
// N=500000, H=256, B=1024, seg_ids sorted ascending.
//
// ONE persistent kernel:
//  phase 1: proven segsum (atomic flushes, 85% DRAM). Blocks 0..63 also
//           write W4T[k4][j] (k-major W copy).
//  barrier: monotonic-ticket grid sync (replay-safe: target derived from
//           ticket/gridDim, counter never reset).
//  phase 2: epilogue GEMM at full residency + warm L2 (the standalone
//           finish kernel floored at 18-27us from launch gap + cold L2 +
//           grid-limited occupancy; R14's per-flush fusion cost ~15us).
//           Warp = 32j x 2segs: 4wf coalesced W4T + 2wf uniform pooled
//           per k4, 8 FFMA. Bias+count+relu folded in. Re-zero via
//           8-sibling arrival counters (proven R9/R13 pattern).
//
// DEADLOCK SAFETY: __launch_bounds__(256, 4) caps regs at 64 -> 4 CTAs/SM
// guaranteed resident; grid = 539 < 4*140 << 592 capacity on 148 SMs.

#define H 256
#define HV 64                  // H/4
#define B 1024
#define RPI 32                 // segsum rows per iteration
#define GRID_TARGET 556        // -> rpb 928 -> grid 539 (co-resident, margin)
#define NTILES 512             // phase 2: 8 j-tiles x 64 seg-tiles

__device__ float g_pooled[B * H];     // [g][k] segment sums (zero-init;
                                      //   re-zeroed by phase 2 each launch)
__device__ float g_count[B];          // nodes per segment (same)
__device__ float g_W4T[H * H];        // [k4][j] k-major W (rewritten/launch)
__device__ unsigned int g_sync;       // monotonic grid-barrier ticket
__device__ unsigned int g_done[64];   // per-seg-tile arrival counters

__device__ __forceinline__ void flush_acc(float4& acc, int cur, int c) {
    float* dst = &g_pooled[cur * H + c * 4];
    atomicAdd(dst + 0, acc.x);
    atomicAdd(dst + 1, acc.y);
    atomicAdd(dst + 2, acc.z);
    atomicAdd(dst + 3, acc.w);
    acc = make_float4(0.f, 0.f, 0.f, 0.f);
}

__global__ void __launch_bounds__(H, 4) fused_kernel(
    const float* __restrict__ x, const int* __restrict__ seg,
    const float* __restrict__ W, const float* __restrict__ bias,
    float* __restrict__ out, int N, int rows_per_block)
{
    const int tid = threadIdx.x;

    // ---- W4T preamble: blocks 0..63 write one float4 per thread ----
    if (blockIdx.x < 64) {
        reinterpret_cast<float4*>(g_W4T)[blockIdx.x * 256 + tid] =
            __ldg(&reinterpret_cast<const float4*>(W)[tid * HV + blockIdx.x]);
    }

    // =================== PHASE 1: segment sum (hot loop) ===================
    {
        int r0 = blockIdx.x * rows_per_block;
        int r1 = min(r0 + rows_per_block, N);
        if (r0 < r1) {
            const int c      = tid & 63;
            const int rowoff = tid >> 6;
            const float4* __restrict__ x4 = reinterpret_cast<const float4*>(x);

            float4 acc = make_float4(0.f, 0.f, 0.f, 0.f);
            int cur       = __ldg(&seg[r0]);
            int run_start = r0;

            int r = r0;
            for (; r + RPI <= r1; r += RPI) {
                size_t base = (size_t)(r + rowoff) * HV + c;
                float4 v0 = __ldg(&x4[base + 0 * 4 * HV]);
                float4 v1 = __ldg(&x4[base + 1 * 4 * HV]);
                float4 v2 = __ldg(&x4[base + 2 * 4 * HV]);
                float4 v3 = __ldg(&x4[base + 3 * 4 * HV]);
                float4 v4 = __ldg(&x4[base + 4 * 4 * HV]);
                float4 v5 = __ldg(&x4[base + 5 * 4 * HV]);
                float4 v6 = __ldg(&x4[base + 6 * 4 * HV]);
                float4 v7 = __ldg(&x4[base + 7 * 4 * HV]);
                int s_last = __ldg(&seg[r + RPI - 1]);

                if (s_last == cur) {
                    acc.x += ((v0.x + v1.x) + (v2.x + v3.x)) + ((v4.x + v5.x) + (v6.x + v7.x));
                    acc.y += ((v0.y + v1.y) + (v2.y + v3.y)) + ((v4.y + v5.y) + (v6.y + v7.y));
                    acc.z += ((v0.z + v1.z) + (v2.z + v3.z)) + ((v4.z + v5.z) + (v6.z + v7.z));
                    acc.w += ((v0.w + v1.w) + (v2.w + v3.w)) + ((v4.w + v5.w) + (v6.w + v7.w));
                } else {
                    float4 vv[8] = {v0, v1, v2, v3, v4, v5, v6, v7};
                    #pragma unroll
                    for (int k = 0; k < RPI; ++k) {
                        int rr = r + k;
                        int s = __ldg(&seg[rr]);
                        if (s != cur) {
                            flush_acc(acc, cur, c);
                            if (tid == 0)
                                atomicAdd(&g_count[cur], (float)(rr - run_start));
                            cur = s; run_start = rr;
                        }
                        if ((k & 3) == rowoff) {
                            float4 v = vv[k >> 2];
                            acc.x += v.x; acc.y += v.y; acc.z += v.z; acc.w += v.w;
                        }
                    }
                }
            }
            for (; r < r1; ++r) {
                int s = __ldg(&seg[r]);
                if (s != cur) {
                    flush_acc(acc, cur, c);
                    if (tid == 0) atomicAdd(&g_count[cur], (float)(r - run_start));
                    cur = s; run_start = r;
                }
                if (rowoff == 0) {
                    float4 v = __ldg(&x4[(size_t)r * HV + c]);
                    acc.x += v.x; acc.y += v.y; acc.z += v.z; acc.w += v.w;
                }
            }
            flush_acc(acc, cur, c);
            if (tid == 0) atomicAdd(&g_count[cur], (float)(r1 - run_start));
        }
    }

    // ================= GRID BARRIER (monotonic ticket) =====================
    __syncthreads();                         // all warps of block done
    if (tid == 0) {
        __threadfence();                     // publish pooled/count/W4T
        unsigned int ticket = atomicAdd(&g_sync, 1u);
        unsigned int target = (ticket / gridDim.x + 1u) * gridDim.x;
        volatile unsigned int* vs = &g_sync;
        while (*vs < target) __nanosleep(64);
    }
    __syncthreads();
    __threadfence();                         // acquire

    // =================== PHASE 2: epilogue GEMM ============================
    // tile = 32 j x 16 segs; 8 j-tiles x 64 seg-tiles = 512 tiles.
    // Warp = 32 j (lane) x 2 segs. Per k4: coalesced W4T LDG.128 (4 wf) +
    // 2 uniform pooled LDG.128 (1 wf each) + 8 FFMA. Named vars -> MLP=6.
    const float4* __restrict__ w4t = reinterpret_cast<const float4*>(g_W4T);
    const float4* __restrict__ p4  = reinterpret_cast<const float4*>(g_pooled);

    for (int tile = blockIdx.x; tile < NTILES; tile += gridDim.x) {
        const int jt = tile & 7;
        const int st = tile >> 3;
        const int j  = jt * 32 + (tid & 31);
        const int ga = st * 16 + (tid >> 5) * 2;
        const int gb = ga + 1;

        const float4* __restrict__ pa4 = p4 + (size_t)ga * HV;
        const float4* __restrict__ pb4 = p4 + (size_t)gb * HV;

        const float bj = __ldg(&bias[j]);
        float acca = g_count[ga] * bj;
        float accb = g_count[gb] * bj;

        for (int k4 = 0; k4 < HV; k4 += 2) {
            float4 w0 = __ldg(&w4t[(k4 + 0) * 256 + j]);
            float4 w1 = __ldg(&w4t[(k4 + 1) * 256 + j]);
            float4 a0 = __ldg(&pa4[k4]);  float4 a1 = __ldg(&pa4[k4 + 1]);
            float4 b0 = __ldg(&pb4[k4]);  float4 b1 = __ldg(&pb4[k4 + 1]);
            acca += w0.x * a0.x + w0.y * a0.y + w0.z * a0.z + w0.w * a0.w
                  + w1.x * a1.x + w1.y * a1.y + w1.z * a1.z + w1.w * a1.w;
            accb += w0.x * b0.x + w0.y * b0.y + w0.z * b0.z + w0.w * b0.w
                  + w1.x * b1.x + w1.y * b1.y + w1.z * b1.z + w1.w * b1.w;
        }

        out[(size_t)ga * H + j] = fmaxf(acca, 0.f);
        out[(size_t)gb * H + j] = fmaxf(accb, 0.f);

        // last of the 8 jt-siblings re-zeros this seg-tile's scratch
        __shared__ int s_last;
        __syncthreads();                     // pooled/count reads complete
        if (tid == 0) {
            __threadfence();
            s_last = (atomicAdd(&g_done[st], 1u) == 7u) ? 1 : 0;
        }
        __syncthreads();
        if (s_last) {
            const float4 z = make_float4(0.f, 0.f, 0.f, 0.f);
            float4* pz = reinterpret_cast<float4*>(g_pooled) + (size_t)st * 16 * HV;
            #pragma unroll
            for (int i = 0; i < 4; ++i)      // 16 segs * 64 float4 = 1024
                pz[tid + i * 256] = z;
            if (tid < 16) g_count[st * 16 + tid] = 0.f;
            if (tid == 0) g_done[st] = 0u;
        }
    }
}

// ---------------------------------------------------------------------------
// Launch
// ---------------------------------------------------------------------------
extern "C" void kernel_launch(void* const* d_in, const int* in_sizes, int n_in,
                              void* d_out, int out_size)
{
    const float* x   = (const float*)d_in[0];   // [N, 256]
    const int*   seg = (const int*)  d_in[1];   // [N]
    const float* W   = (const float*)d_in[2];   // [256, 256]
    const float* b   = (const float*)d_in[3];   // [256]
    float* out = (float*)d_out;                 // [1024, 256]

    const int N = in_sizes[0] / H;

    // grid sized for GUARANTEED co-residency (4 CTAs/SM via launch_bounds):
    // rpb = 928 -> grid = 539 <= 4*140 (margin below the 592 capacity).
    int rpb = (N + GRID_TARGET - 1) / GRID_TARGET;
    rpb = ((rpb + RPI - 1) / RPI) * RPI;        // N=500000 -> 928
    int grid = (N + rpb - 1) / rpb;             // -> 539

    fused_kernel<<<grid, H>>>(x, seg, W, b, out, N, rpb);
}

// round 16
// speedup vs baseline: 1.0365x; 1.0365x over previous
#include <cuda_runtime.h>
#include <cuda_bf16.h>

// relu(segment_sum(x @ W^T + b))  ==  relu(segment_sum(x) @ W^T + count * b)
// N=500000, H=256, B=1024, seg_ids sorted ascending.
//
// TWO kernels (persistent/fused variants measured worse: R14 98.5, R15 99.0
// -- the DRAM phase needs all 1117 blocks; barriers can't have them):
//  1. segsum: proven 77.2us @ 85% DRAM (roofline). First 64 blocks also
//     write the k-major W copy W4T[k4][j].
//  2. finish: R13's memory structure (conflict-free smem W tile read via
//     29-cyc LDS + named uniform pooled LDGs) at 8 warps/block instead of
//     4 -- R13's only measured defect was occ=21% latency exposure.

#define H 256
#define HV 64                  // H/4
#define B 1024
#define TARGET_GRID 1184       // segsum: 148 SMs * 8 blocks ceiling
#define RPI 32                 // segsum rows per iteration
#define FJT 8                  // finish: j tiles (32 j each)
#define FST 64                 // finish: seg tiles (16 segs each)

__device__ float g_pooled[B * H];     // [g][k] segment sums (zero-init)
__device__ float g_count[B];          // nodes per segment   (zero-init)
__device__ float g_W4T[H * H];        // [k4][j] k-major W (overwritten/launch)
__device__ unsigned int g_done[FST];  // per-seg-tile arrival counters (zero-init)

// ---------------------------------------------------------------------------
// Kernel 1: segment-sum of x (row-major pooled).  At HBM roofline.
// ---------------------------------------------------------------------------
__device__ __forceinline__ void flush_acc(float4& acc, int cur, int c) {
    float* dst = &g_pooled[cur * H + c * 4];
    atomicAdd(dst + 0, acc.x);
    atomicAdd(dst + 1, acc.y);
    atomicAdd(dst + 2, acc.z);
    atomicAdd(dst + 3, acc.w);
    acc = make_float4(0.f, 0.f, 0.f, 0.f);
}

__global__ void __launch_bounds__(H) segsum_kernel(
    const float* __restrict__ x, const int* __restrict__ seg,
    const float* __restrict__ W, int N, int rows_per_block)
{
    // preamble: blocks 0..63 write W4T[k4=blockIdx][j=tid] (one float4 each)
    if (blockIdx.x < 64) {
        reinterpret_cast<float4*>(g_W4T)[blockIdx.x * 256 + threadIdx.x] =
            __ldg(&reinterpret_cast<const float4*>(W)[threadIdx.x * HV + blockIdx.x]);
    }

    int r0 = blockIdx.x * rows_per_block;
    int r1 = min(r0 + rows_per_block, N);
    if (r0 >= r1) return;

    const int tid    = threadIdx.x;
    const int c      = tid & 63;
    const int rowoff = tid >> 6;
    const float4* __restrict__ x4 = reinterpret_cast<const float4*>(x);

    float4 acc = make_float4(0.f, 0.f, 0.f, 0.f);
    int cur       = __ldg(&seg[r0]);
    int run_start = r0;

    int r = r0;
    for (; r + RPI <= r1; r += RPI) {
        size_t base = (size_t)(r + rowoff) * HV + c;
        float4 v0 = __ldg(&x4[base + 0 * 4 * HV]);
        float4 v1 = __ldg(&x4[base + 1 * 4 * HV]);
        float4 v2 = __ldg(&x4[base + 2 * 4 * HV]);
        float4 v3 = __ldg(&x4[base + 3 * 4 * HV]);
        float4 v4 = __ldg(&x4[base + 4 * 4 * HV]);
        float4 v5 = __ldg(&x4[base + 5 * 4 * HV]);
        float4 v6 = __ldg(&x4[base + 6 * 4 * HV]);
        float4 v7 = __ldg(&x4[base + 7 * 4 * HV]);
        int s_last = __ldg(&seg[r + RPI - 1]);

        if (s_last == cur) {
            acc.x += ((v0.x + v1.x) + (v2.x + v3.x)) + ((v4.x + v5.x) + (v6.x + v7.x));
            acc.y += ((v0.y + v1.y) + (v2.y + v3.y)) + ((v4.y + v5.y) + (v6.y + v7.y));
            acc.z += ((v0.z + v1.z) + (v2.z + v3.z)) + ((v4.z + v5.z) + (v6.z + v7.z));
            acc.w += ((v0.w + v1.w) + (v2.w + v3.w)) + ((v4.w + v5.w) + (v6.w + v7.w));
        } else {
            float4 vv[8] = {v0, v1, v2, v3, v4, v5, v6, v7};
            #pragma unroll
            for (int k = 0; k < RPI; ++k) {
                int rr = r + k;
                int s = __ldg(&seg[rr]);
                if (s != cur) {
                    flush_acc(acc, cur, c);
                    if (tid == 0)
                        atomicAdd(&g_count[cur], (float)(rr - run_start));
                    cur = s; run_start = rr;
                }
                if ((k & 3) == rowoff) {
                    float4 v = vv[k >> 2];
                    acc.x += v.x; acc.y += v.y; acc.z += v.z; acc.w += v.w;
                }
            }
        }
    }
    for (; r < r1; ++r) {
        int s = __ldg(&seg[r]);
        if (s != cur) {
            flush_acc(acc, cur, c);
            if (tid == 0) atomicAdd(&g_count[cur], (float)(r - run_start));
            cur = s; run_start = r;
        }
        if (rowoff == 0) {
            float4 v = __ldg(&x4[(size_t)r * HV + c]);
            acc.x += v.x; acc.y += v.y; acc.z += v.z; acc.w += v.w;
        }
    }
    flush_acc(acc, cur, c);
    if (tid == 0) atomicAdd(&g_count[cur], (float)(r1 - run_start));
}

// ---------------------------------------------------------------------------
// Kernel 2: finish. 512 blocks (8 jt x 64 st) x 256 threads (8 warps).
// smem: 32KB W tile sws[k4*32 + jl] (float4), staged coalesced,
// conflict-free (consecutive lanes -> consecutive float4).
// Thread: jl = t&31 (one j); warp = t>>5 owns TWO segments (8 warps x 2 =
// 16 segs/block). Body (2 k4): 2 LDS.128 (29cyc) + 4 EXPLICIT NAMED
// uniform pooled LDGs + 64 FFMA. vs R13: same structure, 2x the warps
// (occ 21% -> ~43%) -- R13's only measured defect was latency exposure.
// Last of the 8 jt siblings per seg-tile re-zeros its scratch region.
// ---------------------------------------------------------------------------
__global__ void __launch_bounds__(256) finish_kernel(
    const float* __restrict__ bias, float* __restrict__ out)
{
    const int t  = threadIdx.x;
    const int jt = blockIdx.x & (FJT - 1);
    const int st = blockIdx.x >> 3;
    const int j0 = jt * 32;
    const int g0 = st * 16;
    const int jl = t & 31;
    const int wp = t >> 5;              // 0..7
    const int ga = g0 + wp * 2;
    const int gb = ga + 1;

    __shared__ __align__(16) float4 sws[HV * 32];   // 32KB: sws[k4*32 + jl]

    // ---- stage W4T tile for j in [j0, j0+32): coalesced, conflict-free ----
    {
        const float4* __restrict__ w4t = reinterpret_cast<const float4*>(g_W4T);
        #pragma unroll
        for (int i = 0; i < 8; ++i) {
            int idx = t + i * 256;              // 0..2047
            int k4  = idx >> 5;
            int jj  = idx & 31;
            sws[idx] = __ldg(&w4t[k4 * 256 + j0 + jj]);
        }
    }
    __syncthreads();

    const float4* __restrict__ p4 = reinterpret_cast<const float4*>(g_pooled);
    const float4* __restrict__ pA = p4 + (size_t)ga * HV;
    const float4* __restrict__ pB = p4 + (size_t)gb * HV;

    const float bj = __ldg(&bias[j0 + jl]);
    float accA = g_count[ga] * bj;
    float accB = g_count[gb] * bj;

    for (int k4 = 0; k4 < HV; k4 += 2) {
        // explicit named loads: 2 LDS + 4 uniform LDG all in flight
        float4 w0 = sws[(k4 + 0) * 32 + jl];
        float4 w1 = sws[(k4 + 1) * 32 + jl];
        float4 a0 = __ldg(&pA[k4]);  float4 a1 = __ldg(&pA[k4 + 1]);
        float4 b0 = __ldg(&pB[k4]);  float4 b1 = __ldg(&pB[k4 + 1]);

        accA += w0.x * a0.x + w0.y * a0.y + w0.z * a0.z + w0.w * a0.w
              + w1.x * a1.x + w1.y * a1.y + w1.z * a1.z + w1.w * a1.w;
        accB += w0.x * b0.x + w0.y * b0.y + w0.z * b0.z + w0.w * b0.w
              + w1.x * b1.x + w1.y * b1.y + w1.z * b1.z + w1.w * b1.w;
    }

    const int j = j0 + jl;
    out[(size_t)ga * H + j] = fmaxf(accA, 0.f);
    out[(size_t)gb * H + j] = fmaxf(accB, 0.f);

    // ---- last of the 8 jt siblings re-zeros this seg-tile's scratch ----
    __shared__ int s_last;
    __syncthreads();                    // all pooled/count reads complete
    if (t == 0) {
        __threadfence();
        s_last = (atomicAdd(&g_done[st], 1u) == FJT - 1) ? 1 : 0;
    }
    __syncthreads();
    if (s_last) {
        const float4 z = make_float4(0.f, 0.f, 0.f, 0.f);
        float4* pz = reinterpret_cast<float4*>(g_pooled) + (size_t)g0 * HV;
        #pragma unroll
        for (int i = 0; i < 4; ++i)     // 16 segs * 64 float4 = 1024
            pz[t + i * 256] = z;
        if (t < 16) g_count[g0 + t] = 0.f;
        if (t == 0) g_done[st] = 0u;
    }
}

// ---------------------------------------------------------------------------
// Launch
// ---------------------------------------------------------------------------
extern "C" void kernel_launch(void* const* d_in, const int* in_sizes, int n_in,
                              void* d_out, int out_size)
{
    const float* x   = (const float*)d_in[0];   // [N, 256]
    const int*   seg = (const int*)  d_in[1];   // [N]
    const float* W   = (const float*)d_in[2];   // [256, 256]
    const float* b   = (const float*)d_in[3];   // [256]
    float* out = (float*)d_out;                 // [1024, 256]

    const int N = in_sizes[0] / H;

    int rpb = (N + TARGET_GRID - 1) / TARGET_GRID;
    rpb = ((rpb + RPI - 1) / RPI) * RPI;        // N=500000 -> 448
    int grid = (N + rpb - 1) / rpb;             // -> 1117

    segsum_kernel<<<grid, H>>>(x, seg, W, N, rpb);
    finish_kernel<<<FJT * FST, 256>>>(b, out);
}